// round 12
// baseline (speedup 1.0000x reference)
#include <cuda_runtime.h>
#include <cuda_bf16.h>

#define NSTEP 730
#define NG    2000
#define MU    16
#define NOUT  500
#define PRECS 1e-5f

#define SPf 96000   // params stride per t, in floats (NG*3*MU)
#define SXf 6000    // x stride per t, in floats (NG*3)
#define NLANE 32000 // NG*MU

// Reduced flow: qA[t][g] = mean_mu(Q0+Q1+Q2) * Ai[g]
__device__ float g_qA[NSTEP * NG];

__device__ __forceinline__ float f_lg2(float v) {
    float y; asm("lg2.approx.f32 %0, %1;" : "=f"(y) : "f"(v)); return y;
}
__device__ __forceinline__ float f_ex2(float v) {
    float y; asm("ex2.approx.f32 %0, %1;" : "=f"(y) : "f"(v)); return y;
}

// ---------------------------------------------------------------------------
// Kernel 1: HBV scan. 125 blocks x 256 threads = 32,000 exactly.
// R11 structure (depth-4 single-buffer prefetch, in-loop shuffle mean, fused
// output zeroing) + two chain cuts: pow via ex2(fmaf(beta, lg2(SM), beta*lgC))
// and 3 redundant clamps dropped.
// ---------------------------------------------------------------------------
__global__ __launch_bounds__(256)
void hbv_scan_kernel(const float* __restrict__ x,          // (730, 2000, 3)
                     const float* __restrict__ params,     // (730, 2000, 3, 16)
                     const float* __restrict__ wl,         // (2000, 13, 16)
                     const float* __restrict__ Ai,         // (2000,)
                     const float* __restrict__ Acb,        // (2000,)
                     float* __restrict__ out)              // (730, 500) — zeroed here
{
    int tid = blockIdx.x * 256 + threadIdx.x;   // in [0, 32000)
    int g = tid >> 4;
    int m = tid & 15;

    // ---- zero the output (poisoned to 0xAA; GEMM accumulates with atomics).
    for (int i = tid; i < NSTEP * NOUT; i += NLANE) out[i] = 0.0f;

    // ---- per-(g,m) waterloss parameters, scaled by SCA2 ----
    const float* w = wl + (size_t)g * 13 * MU + m;
    float parFC    = 50.0f   + w[0  * MU] * (1000.0f - 50.0f);
    float parK1    = 0.01f   + w[1  * MU] * (0.5f   - 0.01f);
    float parK2    = 0.001f  + w[2  * MU] * (0.2f   - 0.001f);
    float parLP    = 0.2f    + w[3  * MU] * (1.0f   - 0.2f);
    float parPERC  =           w[4  * MU] * 10.0f;
    float parUZL   =           w[5  * MU] * 100.0f;
    float parTT    = -2.5f   + w[6  * MU] * 5.0f;
    float parCFMAX = 0.5f    + w[7  * MU] * (10.0f  - 0.5f);
    float parCFR   =           w[8  * MU] * 0.1f;
    float parCWH   =           w[9  * MU] * 0.2f;
    float parC     =           w[10 * MU] * 1.0f;
    float parTR    =           w[11 * MU] * 20.0f;
    float parAc    =           w[12 * MU] * 2500.0f;

    float Ac  = Acb[g];
    float Aig = Ai[g] * 0.0625f;

    float rf;
    {
        float c1 = fminf(fmaxf((Ac - parAc) * (1.0f / 1000.0f), -1.0f), 1.0f);
        float ea = fminf(fmaxf(-(Ac - 2500.0f) * (1.0f / 50.0f), -10.0f), 0.0f);
        float e  = expf(ea);
        rf = (Ac < 2500.0f) ? (c1 * parTR) : (e * parTR);
    }

    float invFC   = 1.0f / parFC;
    float invLPFC = 1.0f / (parLP * parFC);
    float CFRCF   = parCFR * parCFMAX;
    float lgFC    = f_lg2(invFC);     // loop-invariant log2 coefficients
    float lgLPFC  = f_lg2(invLPFC);

    float SNOWPACK = 0.001f, MELTWATER = 0.001f, SM = 0.001f, SUZ = 0.001f, SLZ = 0.001f;

    const float* pp = params + g * 48 + m;
    const float* xp = x + g * 3;

    float cB[4], cK[4], cBE[4], cP[4], cT[4], cE[4];

    #pragma unroll
    for (int u = 0; u < 4; u++) {
        cB[u]  = __ldcs(pp + u * SPf);
        cK[u]  = __ldcs(pp + u * SPf + 16);
        cBE[u] = __ldcs(pp + u * SPf + 32);
        cP[u]  = xp[u * SXf + 0];
        cT[u]  = xp[u * SXf + 1];
        cE[u]  = xp[u * SXf + 2];
    }

    const float* pf = pp + 4 * SPf;   // prefetch base (row t=tb+4)
    const float* xf = xp + 4 * SXf;
    float* qrow = g_qA + g;           // output row base

#define HBV_STEP(rbv, rkv, rbev, Ptv, Ttv, Etv, QDST) do {                     \
    float parBETA   = fmaf((rbv),  5.0f,  1.0f);                               \
    float parK0     = fmaf((rkv),  0.85f, 0.05f);                              \
    float parBETAET = fmaf((rbev), 4.7f,  0.3f);                               \
    float bc1 = parBETA   * lgFC;     /* off-chain */                          \
    float bc2 = parBETAET * lgLPFC;   /* off-chain */                          \
    float RAIN = ((Ttv) >= parTT) ? (Ptv) : 0.0f;                              \
    SNOWPACK += (Ptv) - RAIN;                                                  \
    float melt = fminf(fmaxf(parCFMAX * ((Ttv) - parTT), 0.0f), SNOWPACK);     \
    MELTWATER += melt;  SNOWPACK -= melt;                                      \
    float refr = fminf(fmaxf(CFRCF * (parTT - (Ttv)), 0.0f), MELTWATER);       \
    SNOWPACK += refr;   MELTWATER -= refr;                                     \
    float tosoil = fmaxf(MELTWATER - parCWH * SNOWPACK, 0.0f);                 \
    MELTWATER -= tosoil;                                                       \
    float sw = __saturatef(f_ex2(fmaf(parBETA, f_lg2(SM), bc1)));              \
    float rt_ = RAIN + tosoil;                                                 \
    float recharge = rt_ * sw;                                                 \
    SM += rt_ - recharge;                                                      \
    float excess = fmaxf(SM - parFC, 0.0f);                                    \
    SM -= excess;                                                              \
    float ef = __saturatef(f_ex2(fmaf(parBETAET, f_lg2(SM), bc2)));            \
    float ETact = fminf(SM, (Etv) * ef);                                       \
    SM = SM - ETact;                       /* ETact <= SM: clamp dropped */    \
    float cap = fminf(SLZ, parC * SLZ * (1.0f - fminf(SM * invFC, 1.0f)));     \
    SM  = SM + cap;                        /* cap >= 0 */                      \
    SLZ = SLZ - cap;                       /* cap <= SLZ */                    \
    SUZ += recharge + excess;                                                  \
    float PERC = fminf(SUZ, parPERC);                                          \
    SUZ -= PERC;                                                               \
    float Q0 = parK0 * fmaxf(SUZ - parUZL, 0.0f);                              \
    SUZ -= Q0;                                                                 \
    float Q1 = parK1 * SUZ;                                                    \
    SUZ -= Q1;                                                                 \
    SLZ = fmaxf(SLZ + PERC + rf, 0.0f);    /* rf may be < 0: keep */           \
    float Q2 = parK2 * SLZ;                                                    \
    SLZ -= Q2;                                                                 \
    float q_ = Q0 + Q1 + Q2;                                                   \
    q_ += __shfl_xor_sync(0xffffffffu, q_, 8);                                 \
    q_ += __shfl_xor_sync(0xffffffffu, q_, 4);                                 \
    q_ += __shfl_xor_sync(0xffffffffu, q_, 2);                                 \
    q_ += __shfl_xor_sync(0xffffffffu, q_, 1);                                 \
    if (m == 0) (QDST) = q_ * Aig;                                             \
} while (0)

    // Main pipelined loop: tb = 0..720 (t = 0..723); prefetch tb+4..tb+7 <= 727.
    for (int tb = 0; tb <= 720; tb += 4) {
        float nB[4], nK[4], nBE[4], nP[4], nT[4], nE[4];
        #pragma unroll
        for (int u = 0; u < 4; u++) {
            nB[u]  = __ldcs(pf + u * SPf);
            nK[u]  = __ldcs(pf + u * SPf + 16);
            nBE[u] = __ldcs(pf + u * SPf + 32);
            nP[u]  = xf[u * SXf + 0];
            nT[u]  = xf[u * SXf + 1];
            nE[u]  = xf[u * SXf + 2];
        }
        pf += 4 * SPf;
        xf += 4 * SXf;

        #pragma unroll
        for (int u = 0; u < 4; u++)
            HBV_STEP(cB[u], cK[u], cBE[u], cP[u], cT[u], cE[u], qrow[u * NG]);
        qrow += 4 * NG;

        #pragma unroll
        for (int u = 0; u < 4; u++) {
            cB[u] = nB[u]; cK[u] = nK[u]; cBE[u] = nBE[u];
            cP[u] = nP[u]; cT[u] = nT[u]; cE[u]  = nE[u];
        }
    }

    // Tail: c holds t = 724..727; pf/xf point at row 728.
    float tB0 = __ldcs(pf + 0),   tK0 = __ldcs(pf + 16),        tBE0 = __ldcs(pf + 32);
    float tP0 = xf[0],            tT0 = xf[1],                  tE0  = xf[2];
    float tB1 = __ldcs(pf + SPf), tK1 = __ldcs(pf + SPf + 16),  tBE1 = __ldcs(pf + SPf + 32);
    float tP1 = xf[SXf],          tT1 = xf[SXf + 1],            tE1  = xf[SXf + 2];

    #pragma unroll
    for (int u = 0; u < 4; u++)
        HBV_STEP(cB[u], cK[u], cBE[u], cP[u], cT[u], cE[u], qrow[u * NG]);
    HBV_STEP(tB0, tK0, tBE0, tP0, tT0, tE0, qrow[4 * NG]);
    HBV_STEP(tB1, tK1, tBE1, tP1, tT1, tE1, qrow[5 * NG]);

#undef HBV_STEP
}

// ---------------------------------------------------------------------------
// Kernel 2: out[t][o] += sum_{g in chunk} qA[t][g] * idx[g][o]
// SGEMM M=730, N=500, K=2000. BM=64, BN=64, BK=32, 256 threads, 4x4/thread,
// split-K=8 (768 blocks). k-major sA: A fragment = ONE LDS.128.
// ---------------------------------------------------------------------------
#define BM 64
#define BN 64
#define BK 32
#define SPLITK 8
#define KCHUNK 250   // 250*8 = 2000 exactly

__global__ __launch_bounds__(256)
void agg_gemm_kernel(const float* __restrict__ idxm,  // (2000, 500)
                     float* __restrict__ out)         // (730, 500)
{
    __shared__ float sA[BK][BM + 4];   // k-major; row stride 68 floats (16B mult)
    __shared__ float sB[BK][BN];       // k-major

    int bm = blockIdx.y * BM;
    int bn = blockIdx.x * BN;
    int kstart = blockIdx.z * KCHUNK;
    int kend   = kstart + KCHUNK;      // always <= NG (250*8 = 2000)

    int tid = threadIdx.x;
    int tx = tid & 15;   // n groups of 4
    int ty = tid >> 4;   // m groups of 4

    float acc[4][4] = {};

    for (int k0 = kstart; k0 < kend; k0 += BK) {
        // A tile: consecutive threads -> consecutive kk (gmem coalesced).
        #pragma unroll
        for (int i = tid; i < BM * BK; i += 256) {
            int mm = i >> 5;
            int kk = i & 31;
            int t = bm + mm;
            int k = k0 + kk;
            sA[kk][mm] = (t < NSTEP && k < kend) ? g_qA[(size_t)t * NG + k] : 0.0f;
        }
        // B tile: consecutive threads -> consecutive nn (gmem coalesced)
        #pragma unroll
        for (int i = tid; i < BK * BN; i += 256) {
            int kk = i >> 6;
            int nn = i & 63;
            int k = k0 + kk;
            int o = bn + nn;
            sB[kk][nn] = (k < kend && o < NOUT) ? idxm[(size_t)k * NOUT + o] : 0.0f;
        }
        __syncthreads();

        #pragma unroll 8
        for (int k = 0; k < BK; k++) {
            float4 a4 = *reinterpret_cast<const float4*>(&sA[k][ty * 4]);
            float4 b4 = *reinterpret_cast<const float4*>(&sB[k][tx * 4]);
            float aa[4] = {a4.x, a4.y, a4.z, a4.w};
            float bb[4] = {b4.x, b4.y, b4.z, b4.w};
            #pragma unroll
            for (int i = 0; i < 4; i++)
                #pragma unroll
                for (int j = 0; j < 4; j++)
                    acc[i][j] = fmaf(aa[i], bb[j], acc[i][j]);
        }
        __syncthreads();
    }

    #pragma unroll
    for (int i = 0; i < 4; i++) {
        int t = bm + ty * 4 + i;
        if (t >= NSTEP) continue;
        #pragma unroll
        for (int j = 0; j < 4; j++) {
            int o = bn + tx * 4 + j;
            if (o < NOUT) atomicAdd(&out[(size_t)t * NOUT + o], acc[i][j]);
        }
    }
}

// ---------------------------------------------------------------------------
extern "C" void kernel_launch(void* const* d_in, const int* in_sizes, int n_in,
                              void* d_out, int out_size) {
    const float* x      = (const float*)d_in[0];  // (730,2000,3)
    const float* params = (const float*)d_in[1];  // (730,2000,3,16)
    const float* wl     = (const float*)d_in[2];  // (2000,13,16)
    const float* Ai     = (const float*)d_in[3];  // (2000,)
    const float* Acb    = (const float*)d_in[4];  // (2000,)
    const float* idxm   = (const float*)d_in[5];  // (2000,500)
    float* out = (float*)d_out;                   // (730,500,1)

    hbv_scan_kernel<<<125, 256>>>(x, params, wl, Ai, Acb, out);

    dim3 grid((NOUT + BN - 1) / BN, (NSTEP + BM - 1) / BM, SPLITK);
    agg_gemm_kernel<<<grid, 256>>>(idxm, out);
}

// round 13
// speedup vs baseline: 1.0342x; 1.0342x over previous
#include <cuda_runtime.h>
#include <cuda_bf16.h>

#define NSTEP 730
#define NG    2000
#define MU    16
#define NOUT  500
#define PRECS 1e-5f

#define SPf 96000   // params stride per t, in floats (NG*3*MU)
#define SXf 6000    // x stride per t, in floats (NG*3)
#define NLANE 32000 // NG*MU

// Reduced flow: qA[t][g] = mean_mu(Q0+Q1+Q2) * Ai[g]
__device__ float g_qA[NSTEP * NG];

__device__ __forceinline__ float f_lg2(float v) {
    float y; asm("lg2.approx.f32 %0, %1;" : "=f"(y) : "f"(v)); return y;
}
__device__ __forceinline__ float f_ex2(float v) {
    float y; asm("ex2.approx.f32 %0, %1;" : "=f"(y) : "f"(v)); return y;
}

// ---------------------------------------------------------------------------
// Kernel 1: HBV scan (R12 measured winner: ~159us). 125 x 256 = 32,000 lanes.
// Depth-4 single-buffer prefetch, in-loop shuffle mean, fused output zeroing,
// pow via ex2(fmaf(beta, lg2(SM), beta*lgC)) with coefficient off-chain,
// 3 provably-redundant clamps dropped.
// ---------------------------------------------------------------------------
__global__ __launch_bounds__(256)
void hbv_scan_kernel(const float* __restrict__ x,          // (730, 2000, 3)
                     const float* __restrict__ params,     // (730, 2000, 3, 16)
                     const float* __restrict__ wl,         // (2000, 13, 16)
                     const float* __restrict__ Ai,         // (2000,)
                     const float* __restrict__ Acb,        // (2000,)
                     float* __restrict__ out)              // (730, 500) — zeroed here
{
    int tid = blockIdx.x * 256 + threadIdx.x;   // in [0, 32000)
    int g = tid >> 4;
    int m = tid & 15;

    // ---- zero the output (poisoned to 0xAA; GEMM accumulates with atomics).
    for (int i = tid; i < NSTEP * NOUT; i += NLANE) out[i] = 0.0f;

    // ---- per-(g,m) waterloss parameters, scaled by SCA2 ----
    const float* w = wl + (size_t)g * 13 * MU + m;
    float parFC    = 50.0f   + w[0  * MU] * (1000.0f - 50.0f);
    float parK1    = 0.01f   + w[1  * MU] * (0.5f   - 0.01f);
    float parK2    = 0.001f  + w[2  * MU] * (0.2f   - 0.001f);
    float parLP    = 0.2f    + w[3  * MU] * (1.0f   - 0.2f);
    float parPERC  =           w[4  * MU] * 10.0f;
    float parUZL   =           w[5  * MU] * 100.0f;
    float parTT    = -2.5f   + w[6  * MU] * 5.0f;
    float parCFMAX = 0.5f    + w[7  * MU] * (10.0f  - 0.5f);
    float parCFR   =           w[8  * MU] * 0.1f;
    float parCWH   =           w[9  * MU] * 0.2f;
    float parC     =           w[10 * MU] * 1.0f;
    float parTR    =           w[11 * MU] * 20.0f;
    float parAc    =           w[12 * MU] * 2500.0f;

    float Ac  = Acb[g];
    float Aig = Ai[g] * 0.0625f;

    float rf;
    {
        float c1 = fminf(fmaxf((Ac - parAc) * (1.0f / 1000.0f), -1.0f), 1.0f);
        float ea = fminf(fmaxf(-(Ac - 2500.0f) * (1.0f / 50.0f), -10.0f), 0.0f);
        float e  = expf(ea);
        rf = (Ac < 2500.0f) ? (c1 * parTR) : (e * parTR);
    }

    float invFC   = 1.0f / parFC;
    float invLPFC = 1.0f / (parLP * parFC);
    float CFRCF   = parCFR * parCFMAX;
    float lgFC    = f_lg2(invFC);     // loop-invariant log2 coefficients
    float lgLPFC  = f_lg2(invLPFC);

    float SNOWPACK = 0.001f, MELTWATER = 0.001f, SM = 0.001f, SUZ = 0.001f, SLZ = 0.001f;

    const float* pp = params + g * 48 + m;
    const float* xp = x + g * 3;

    float cB[4], cK[4], cBE[4], cP[4], cT[4], cE[4];

    #pragma unroll
    for (int u = 0; u < 4; u++) {
        cB[u]  = __ldcs(pp + u * SPf);
        cK[u]  = __ldcs(pp + u * SPf + 16);
        cBE[u] = __ldcs(pp + u * SPf + 32);
        cP[u]  = xp[u * SXf + 0];
        cT[u]  = xp[u * SXf + 1];
        cE[u]  = xp[u * SXf + 2];
    }

    const float* pf = pp + 4 * SPf;   // prefetch base (row t=tb+4)
    const float* xf = xp + 4 * SXf;
    float* qrow = g_qA + g;           // output row base

#define HBV_STEP(rbv, rkv, rbev, Ptv, Ttv, Etv, QDST) do {                     \
    float parBETA   = fmaf((rbv),  5.0f,  1.0f);                               \
    float parK0     = fmaf((rkv),  0.85f, 0.05f);                              \
    float parBETAET = fmaf((rbev), 4.7f,  0.3f);                               \
    float bc1 = parBETA   * lgFC;     /* off-chain */                          \
    float bc2 = parBETAET * lgLPFC;   /* off-chain */                          \
    float RAIN = ((Ttv) >= parTT) ? (Ptv) : 0.0f;                              \
    SNOWPACK += (Ptv) - RAIN;                                                  \
    float melt = fminf(fmaxf(parCFMAX * ((Ttv) - parTT), 0.0f), SNOWPACK);     \
    MELTWATER += melt;  SNOWPACK -= melt;                                      \
    float refr = fminf(fmaxf(CFRCF * (parTT - (Ttv)), 0.0f), MELTWATER);       \
    SNOWPACK += refr;   MELTWATER -= refr;                                     \
    float tosoil = fmaxf(MELTWATER - parCWH * SNOWPACK, 0.0f);                 \
    MELTWATER -= tosoil;                                                       \
    float sw = __saturatef(f_ex2(fmaf(parBETA, f_lg2(SM), bc1)));              \
    float rt_ = RAIN + tosoil;                                                 \
    float recharge = rt_ * sw;                                                 \
    SM += rt_ - recharge;                                                      \
    float excess = fmaxf(SM - parFC, 0.0f);                                    \
    SM -= excess;                                                              \
    float ef = __saturatef(f_ex2(fmaf(parBETAET, f_lg2(SM), bc2)));            \
    float ETact = fminf(SM, (Etv) * ef);                                       \
    SM = SM - ETact;                       /* ETact <= SM: clamp dropped */    \
    float cap = fminf(SLZ, parC * SLZ * (1.0f - fminf(SM * invFC, 1.0f)));     \
    SM  = SM + cap;                        /* cap >= 0 */                      \
    SLZ = SLZ - cap;                       /* cap <= SLZ */                    \
    SUZ += recharge + excess;                                                  \
    float PERC = fminf(SUZ, parPERC);                                          \
    SUZ -= PERC;                                                               \
    float Q0 = parK0 * fmaxf(SUZ - parUZL, 0.0f);                              \
    SUZ -= Q0;                                                                 \
    float Q1 = parK1 * SUZ;                                                    \
    SUZ -= Q1;                                                                 \
    SLZ = fmaxf(SLZ + PERC + rf, 0.0f);    /* rf may be < 0: keep */           \
    float Q2 = parK2 * SLZ;                                                    \
    SLZ -= Q2;                                                                 \
    float q_ = Q0 + Q1 + Q2;                                                   \
    q_ += __shfl_xor_sync(0xffffffffu, q_, 8);                                 \
    q_ += __shfl_xor_sync(0xffffffffu, q_, 4);                                 \
    q_ += __shfl_xor_sync(0xffffffffu, q_, 2);                                 \
    q_ += __shfl_xor_sync(0xffffffffu, q_, 1);                                 \
    if (m == 0) (QDST) = q_ * Aig;                                             \
} while (0)

    // Main pipelined loop: tb = 0..720 (t = 0..723); prefetch tb+4..tb+7 <= 727.
    for (int tb = 0; tb <= 720; tb += 4) {
        float nB[4], nK[4], nBE[4], nP[4], nT[4], nE[4];
        #pragma unroll
        for (int u = 0; u < 4; u++) {
            nB[u]  = __ldcs(pf + u * SPf);
            nK[u]  = __ldcs(pf + u * SPf + 16);
            nBE[u] = __ldcs(pf + u * SPf + 32);
            nP[u]  = xf[u * SXf + 0];
            nT[u]  = xf[u * SXf + 1];
            nE[u]  = xf[u * SXf + 2];
        }
        pf += 4 * SPf;
        xf += 4 * SXf;

        #pragma unroll
        for (int u = 0; u < 4; u++)
            HBV_STEP(cB[u], cK[u], cBE[u], cP[u], cT[u], cE[u], qrow[u * NG]);
        qrow += 4 * NG;

        #pragma unroll
        for (int u = 0; u < 4; u++) {
            cB[u] = nB[u]; cK[u] = nK[u]; cBE[u] = nBE[u];
            cP[u] = nP[u]; cT[u] = nT[u]; cE[u]  = nE[u];
        }
    }

    // Tail: c holds t = 724..727; pf/xf point at row 728.
    float tB0 = __ldcs(pf + 0),   tK0 = __ldcs(pf + 16),        tBE0 = __ldcs(pf + 32);
    float tP0 = xf[0],            tT0 = xf[1],                  tE0  = xf[2];
    float tB1 = __ldcs(pf + SPf), tK1 = __ldcs(pf + SPf + 16),  tBE1 = __ldcs(pf + SPf + 32);
    float tP1 = xf[SXf],          tT1 = xf[SXf + 1],            tE1  = xf[SXf + 2];

    #pragma unroll
    for (int u = 0; u < 4; u++)
        HBV_STEP(cB[u], cK[u], cBE[u], cP[u], cT[u], cE[u], qrow[u * NG]);
    HBV_STEP(tB0, tK0, tBE0, tP0, tT0, tE0, qrow[4 * NG]);
    HBV_STEP(tB1, tK1, tBE1, tP1, tT1, tE1, qrow[5 * NG]);

#undef HBV_STEP
}

// ---------------------------------------------------------------------------
// Kernel 2: out[t][o] += sum_{g in chunk} qA[t][g] * idx[g][o]
// SGEMM M=730, N=500, K=2000. R11 measured winner (55.1us): BM=64, BN=64,
// BK=32, 256 threads, 4x4/thread, split-K=6 (576 blocks), k-major sA with
// LDS.128 A-fragment loads.
// ---------------------------------------------------------------------------
#define BM 64
#define BN 64
#define BK 32
#define SPLITK 6
#define KCHUNK 336   // 336*6 = 2016 >= 2000

__global__ __launch_bounds__(256)
void agg_gemm_kernel(const float* __restrict__ idxm,  // (2000, 500)
                     float* __restrict__ out)         // (730, 500)
{
    __shared__ float sA[BK][BM + 4];   // k-major; row stride 68 floats (16B mult)
    __shared__ float sB[BK][BN];       // k-major

    int bm = blockIdx.y * BM;
    int bn = blockIdx.x * BN;
    int kstart = blockIdx.z * KCHUNK;
    int kend   = min(kstart + KCHUNK, NG);

    int tid = threadIdx.x;
    int tx = tid & 15;   // n groups of 4
    int ty = tid >> 4;   // m groups of 4

    float acc[4][4] = {};

    for (int k0 = kstart; k0 < kend; k0 += BK) {
        // A tile: consecutive threads -> consecutive kk (gmem coalesced).
        #pragma unroll
        for (int i = tid; i < BM * BK; i += 256) {
            int mm = i >> 5;
            int kk = i & 31;
            int t = bm + mm;
            int k = k0 + kk;
            sA[kk][mm] = (t < NSTEP && k < kend) ? g_qA[(size_t)t * NG + k] : 0.0f;
        }
        // B tile: consecutive threads -> consecutive nn (gmem coalesced)
        #pragma unroll
        for (int i = tid; i < BK * BN; i += 256) {
            int kk = i >> 6;
            int nn = i & 63;
            int k = k0 + kk;
            int o = bn + nn;
            sB[kk][nn] = (k < kend && o < NOUT) ? idxm[(size_t)k * NOUT + o] : 0.0f;
        }
        __syncthreads();

        #pragma unroll 8
        for (int k = 0; k < BK; k++) {
            float4 a4 = *reinterpret_cast<const float4*>(&sA[k][ty * 4]);
            float4 b4 = *reinterpret_cast<const float4*>(&sB[k][tx * 4]);
            float aa[4] = {a4.x, a4.y, a4.z, a4.w};
            float bb[4] = {b4.x, b4.y, b4.z, b4.w};
            #pragma unroll
            for (int i = 0; i < 4; i++)
                #pragma unroll
                for (int j = 0; j < 4; j++)
                    acc[i][j] = fmaf(aa[i], bb[j], acc[i][j]);
        }
        __syncthreads();
    }

    #pragma unroll
    for (int i = 0; i < 4; i++) {
        int t = bm + ty * 4 + i;
        if (t >= NSTEP) continue;
        #pragma unroll
        for (int j = 0; j < 4; j++) {
            int o = bn + tx * 4 + j;
            if (o < NOUT) atomicAdd(&out[(size_t)t * NOUT + o], acc[i][j]);
        }
    }
}

// ---------------------------------------------------------------------------
extern "C" void kernel_launch(void* const* d_in, const int* in_sizes, int n_in,
                              void* d_out, int out_size) {
    const float* x      = (const float*)d_in[0];  // (730,2000,3)
    const float* params = (const float*)d_in[1];  // (730,2000,3,16)
    const float* wl     = (const float*)d_in[2];  // (2000,13,16)
    const float* Ai     = (const float*)d_in[3];  // (2000,)
    const float* Acb    = (const float*)d_in[4];  // (2000,)
    const float* idxm   = (const float*)d_in[5];  // (2000,500)
    float* out = (float*)d_out;                   // (730,500,1)

    hbv_scan_kernel<<<125, 256>>>(x, params, wl, Ai, Acb, out);

    dim3 grid((NOUT + BN - 1) / BN, (NSTEP + BM - 1) / BM, SPLITK);
    agg_gemm_kernel<<<grid, 256>>>(idxm, out);
}

// round 14
// speedup vs baseline: 1.0357x; 1.0015x over previous
#include <cuda_runtime.h>
#include <cuda_bf16.h>

#define NSTEP 730
#define NG    2000
#define MU    16
#define NOUT  500
#define PRECS 1e-5f

#define SPf 96000   // params stride per t, in floats (NG*3*MU)
#define SXf 6000    // x stride per t, in floats (NG*3)
#define NLANE 32000 // NG*MU

// Reduced flow: qA[t][g] = mean_mu(Q0+Q1+Q2) * Ai[g]
__device__ float g_qA[NSTEP * NG];

__device__ __forceinline__ float f_lg2(float v) {
    float y; asm("lg2.approx.f32 %0, %1;" : "=f"(y) : "f"(v)); return y;
}
__device__ __forceinline__ float f_ex2(float v) {
    float y; asm("ex2.approx.f32 %0, %1;" : "=f"(y) : "f"(v)); return y;
}

// ---------------------------------------------------------------------------
// Kernel 1: HBV scan. 125 x 256 = 32,000 lanes. R13 structure plus two
// SM-chain cuts: (a) ETact = min(min(SM,Et), ex2(fmaf(bET, lg2(SM), bc2+lg2Et)))
// with lg2(Et) precomputed off-chain from the prefetched Et; (b) capillary
// factor via fmaxf(fmaf(-SM, invFC, 1), 0) with parC*SLZ hoisted off-chain.
// ---------------------------------------------------------------------------
__global__ __launch_bounds__(256)
void hbv_scan_kernel(const float* __restrict__ x,          // (730, 2000, 3)
                     const float* __restrict__ params,     // (730, 2000, 3, 16)
                     const float* __restrict__ wl,         // (2000, 13, 16)
                     const float* __restrict__ Ai,         // (2000,)
                     const float* __restrict__ Acb,        // (2000,)
                     float* __restrict__ out)              // (730, 500) — zeroed here
{
    int tid = blockIdx.x * 256 + threadIdx.x;   // in [0, 32000)
    int g = tid >> 4;
    int m = tid & 15;

    // ---- zero the output (poisoned to 0xAA; GEMM accumulates with atomics).
    for (int i = tid; i < NSTEP * NOUT; i += NLANE) out[i] = 0.0f;

    // ---- per-(g,m) waterloss parameters, scaled by SCA2 ----
    const float* w = wl + (size_t)g * 13 * MU + m;
    float parFC    = 50.0f   + w[0  * MU] * (1000.0f - 50.0f);
    float parK1    = 0.01f   + w[1  * MU] * (0.5f   - 0.01f);
    float parK2    = 0.001f  + w[2  * MU] * (0.2f   - 0.001f);
    float parLP    = 0.2f    + w[3  * MU] * (1.0f   - 0.2f);
    float parPERC  =           w[4  * MU] * 10.0f;
    float parUZL   =           w[5  * MU] * 100.0f;
    float parTT    = -2.5f   + w[6  * MU] * 5.0f;
    float parCFMAX = 0.5f    + w[7  * MU] * (10.0f  - 0.5f);
    float parCFR   =           w[8  * MU] * 0.1f;
    float parCWH   =           w[9  * MU] * 0.2f;
    float parC     =           w[10 * MU] * 1.0f;
    float parTR    =           w[11 * MU] * 20.0f;
    float parAc    =           w[12 * MU] * 2500.0f;

    float Ac  = Acb[g];
    float Aig = Ai[g] * 0.0625f;

    float rf;
    {
        float c1 = fminf(fmaxf((Ac - parAc) * (1.0f / 1000.0f), -1.0f), 1.0f);
        float ea = fminf(fmaxf(-(Ac - 2500.0f) * (1.0f / 50.0f), -10.0f), 0.0f);
        float e  = expf(ea);
        rf = (Ac < 2500.0f) ? (c1 * parTR) : (e * parTR);
    }

    float invFC   = 1.0f / parFC;
    float invLPFC = 1.0f / (parLP * parFC);
    float CFRCF   = parCFR * parCFMAX;
    float lgFC    = f_lg2(invFC);     // loop-invariant log2 coefficients
    float lgLPFC  = f_lg2(invLPFC);

    float SNOWPACK = 0.001f, MELTWATER = 0.001f, SM = 0.001f, SUZ = 0.001f, SLZ = 0.001f;

    const float* pp = params + g * 48 + m;
    const float* xp = x + g * 3;

    float cB[4], cK[4], cBE[4], cP[4], cT[4], cE[4], cLE[4];

    #pragma unroll
    for (int u = 0; u < 4; u++) {
        cB[u]  = __ldcs(pp + u * SPf);
        cK[u]  = __ldcs(pp + u * SPf + 16);
        cBE[u] = __ldcs(pp + u * SPf + 32);
        cP[u]  = xp[u * SXf + 0];
        cT[u]  = xp[u * SXf + 1];
        cE[u]  = xp[u * SXf + 2];
        cLE[u] = f_lg2(cE[u]);
    }

    const float* pf = pp + 4 * SPf;   // prefetch base (row t=tb+4)
    const float* xf = xp + 4 * SXf;
    float* qrow = g_qA + g;           // output row base

#define HBV_STEP(rbv, rkv, rbev, Ptv, Ttv, Etv, LEtv, QDST) do {               \
    float parBETA   = fmaf((rbv),  5.0f,  1.0f);                               \
    float parK0     = fmaf((rkv),  0.85f, 0.05f);                              \
    float parBETAET = fmaf((rbev), 4.7f,  0.3f);                               \
    float bc1  = parBETA   * lgFC;                 /* off-chain */             \
    float bc2e = fmaf(parBETAET, lgLPFC, (LEtv));  /* off-chain, + lg2(Et) */  \
    float pcSLZ = parC * SLZ;                      /* off-chain (prev SLZ) */  \
    float RAIN = ((Ttv) >= parTT) ? (Ptv) : 0.0f;                              \
    SNOWPACK += (Ptv) - RAIN;                                                  \
    float melt = fminf(fmaxf(parCFMAX * ((Ttv) - parTT), 0.0f), SNOWPACK);     \
    MELTWATER += melt;  SNOWPACK -= melt;                                      \
    float refr = fminf(fmaxf(CFRCF * (parTT - (Ttv)), 0.0f), MELTWATER);       \
    SNOWPACK += refr;   MELTWATER -= refr;                                     \
    float tosoil = fmaxf(MELTWATER - parCWH * SNOWPACK, 0.0f);                 \
    MELTWATER -= tosoil;                                                       \
    float sw = __saturatef(f_ex2(fmaf(parBETA, f_lg2(SM), bc1)));              \
    float rt_ = RAIN + tosoil;                                                 \
    float recharge = rt_ * sw;                                                 \
    SM += rt_ - recharge;                                                      \
    float excess = fmaxf(SM - parFC, 0.0f);                                    \
    SM -= excess;                                                              \
    /* ETact = min(SM, Et * saturate(pow)) = min(min(SM,Et), Et*pow) */        \
    float etp = f_ex2(fmaf(parBETAET, f_lg2(SM), bc2e));                       \
    float ETact = fminf(fminf(SM, (Etv)), etp);                                \
    SM = SM - ETact;                       /* ETact <= SM: clamp dropped */    \
    float capf = fmaxf(fmaf(-SM, invFC, 1.0f), 0.0f);                          \
    float cap = fminf(SLZ, pcSLZ * capf);                                      \
    SM  = SM + cap;                        /* cap >= 0 */                      \
    SLZ = SLZ - cap;                       /* cap <= SLZ */                    \
    SUZ += recharge + excess;                                                  \
    float PERC = fminf(SUZ, parPERC);                                          \
    SUZ -= PERC;                                                               \
    float Q0 = parK0 * fmaxf(SUZ - parUZL, 0.0f);                              \
    SUZ -= Q0;                                                                 \
    float Q1 = parK1 * SUZ;                                                    \
    SUZ -= Q1;                                                                 \
    SLZ = fmaxf(SLZ + PERC + rf, 0.0f);    /* rf may be < 0: keep */           \
    float Q2 = parK2 * SLZ;                                                    \
    SLZ -= Q2;                                                                 \
    float q_ = Q0 + Q1 + Q2;                                                   \
    q_ += __shfl_xor_sync(0xffffffffu, q_, 8);                                 \
    q_ += __shfl_xor_sync(0xffffffffu, q_, 4);                                 \
    q_ += __shfl_xor_sync(0xffffffffu, q_, 2);                                 \
    q_ += __shfl_xor_sync(0xffffffffu, q_, 1);                                 \
    if (m == 0) (QDST) = q_ * Aig;                                             \
} while (0)

    // Main pipelined loop: tb = 0..720 (t = 0..723); prefetch tb+4..tb+7 <= 727.
    for (int tb = 0; tb <= 720; tb += 4) {
        float nB[4], nK[4], nBE[4], nP[4], nT[4], nE[4], nLE[4];
        #pragma unroll
        for (int u = 0; u < 4; u++) {
            nB[u]  = __ldcs(pf + u * SPf);
            nK[u]  = __ldcs(pf + u * SPf + 16);
            nBE[u] = __ldcs(pf + u * SPf + 32);
            nP[u]  = xf[u * SXf + 0];
            nT[u]  = xf[u * SXf + 1];
            nE[u]  = xf[u * SXf + 2];
        }
        pf += 4 * SPf;
        xf += 4 * SXf;
        #pragma unroll
        for (int u = 0; u < 4; u++) nLE[u] = f_lg2(nE[u]);

        #pragma unroll
        for (int u = 0; u < 4; u++)
            HBV_STEP(cB[u], cK[u], cBE[u], cP[u], cT[u], cE[u], cLE[u], qrow[u * NG]);
        qrow += 4 * NG;

        #pragma unroll
        for (int u = 0; u < 4; u++) {
            cB[u] = nB[u]; cK[u] = nK[u]; cBE[u] = nBE[u];
            cP[u] = nP[u]; cT[u] = nT[u]; cE[u]  = nE[u]; cLE[u] = nLE[u];
        }
    }

    // Tail: c holds t = 724..727; pf/xf point at row 728.
    float tB0 = __ldcs(pf + 0),   tK0 = __ldcs(pf + 16),        tBE0 = __ldcs(pf + 32);
    float tP0 = xf[0],            tT0 = xf[1],                  tE0  = xf[2];
    float tB1 = __ldcs(pf + SPf), tK1 = __ldcs(pf + SPf + 16),  tBE1 = __ldcs(pf + SPf + 32);
    float tP1 = xf[SXf],          tT1 = xf[SXf + 1],            tE1  = xf[SXf + 2];
    float tLE0 = f_lg2(tE0), tLE1 = f_lg2(tE1);

    #pragma unroll
    for (int u = 0; u < 4; u++)
        HBV_STEP(cB[u], cK[u], cBE[u], cP[u], cT[u], cE[u], cLE[u], qrow[u * NG]);
    HBV_STEP(tB0, tK0, tBE0, tP0, tT0, tE0, tLE0, qrow[4 * NG]);
    HBV_STEP(tB1, tK1, tBE1, tP1, tT1, tE1, tLE1, qrow[5 * NG]);

#undef HBV_STEP
}

// ---------------------------------------------------------------------------
// Kernel 2: out[t][o] += sum_{g in chunk} qA[t][g] * idx[g][o]
// SGEMM M=730, N=500, K=2000. R11/R13 measured winner (55.1-55.7us): BM=64,
// BN=64, BK=32, 256 threads, 4x4/thread, split-K=6 (576 blocks), k-major sA
// with LDS.128 A-fragment loads. UNCHANGED.
// ---------------------------------------------------------------------------
#define BM 64
#define BN 64
#define BK 32
#define SPLITK 6
#define KCHUNK 336   // 336*6 = 2016 >= 2000

__global__ __launch_bounds__(256)
void agg_gemm_kernel(const float* __restrict__ idxm,  // (2000, 500)
                     float* __restrict__ out)         // (730, 500)
{
    __shared__ float sA[BK][BM + 4];   // k-major; row stride 68 floats (16B mult)
    __shared__ float sB[BK][BN];       // k-major

    int bm = blockIdx.y * BM;
    int bn = blockIdx.x * BN;
    int kstart = blockIdx.z * KCHUNK;
    int kend   = min(kstart + KCHUNK, NG);

    int tid = threadIdx.x;
    int tx = tid & 15;   // n groups of 4
    int ty = tid >> 4;   // m groups of 4

    float acc[4][4] = {};

    for (int k0 = kstart; k0 < kend; k0 += BK) {
        // A tile: consecutive threads -> consecutive kk (gmem coalesced).
        #pragma unroll
        for (int i = tid; i < BM * BK; i += 256) {
            int mm = i >> 5;
            int kk = i & 31;
            int t = bm + mm;
            int k = k0 + kk;
            sA[kk][mm] = (t < NSTEP && k < kend) ? g_qA[(size_t)t * NG + k] : 0.0f;
        }
        // B tile: consecutive threads -> consecutive nn (gmem coalesced)
        #pragma unroll
        for (int i = tid; i < BK * BN; i += 256) {
            int kk = i >> 6;
            int nn = i & 63;
            int k = k0 + kk;
            int o = bn + nn;
            sB[kk][nn] = (k < kend && o < NOUT) ? idxm[(size_t)k * NOUT + o] : 0.0f;
        }
        __syncthreads();

        #pragma unroll 8
        for (int k = 0; k < BK; k++) {
            float4 a4 = *reinterpret_cast<const float4*>(&sA[k][ty * 4]);
            float4 b4 = *reinterpret_cast<const float4*>(&sB[k][tx * 4]);
            float aa[4] = {a4.x, a4.y, a4.z, a4.w};
            float bb[4] = {b4.x, b4.y, b4.z, b4.w};
            #pragma unroll
            for (int i = 0; i < 4; i++)
                #pragma unroll
                for (int j = 0; j < 4; j++)
                    acc[i][j] = fmaf(aa[i], bb[j], acc[i][j]);
        }
        __syncthreads();
    }

    #pragma unroll
    for (int i = 0; i < 4; i++) {
        int t = bm + ty * 4 + i;
        if (t >= NSTEP) continue;
        #pragma unroll
        for (int j = 0; j < 4; j++) {
            int o = bn + tx * 4 + j;
            if (o < NOUT) atomicAdd(&out[(size_t)t * NOUT + o], acc[i][j]);
        }
    }
}

// ---------------------------------------------------------------------------
extern "C" void kernel_launch(void* const* d_in, const int* in_sizes, int n_in,
                              void* d_out, int out_size) {
    const float* x      = (const float*)d_in[0];  // (730,2000,3)
    const float* params = (const float*)d_in[1];  // (730,2000,3,16)
    const float* wl     = (const float*)d_in[2];  // (2000,13,16)
    const float* Ai     = (const float*)d_in[3];  // (2000,)
    const float* Acb    = (const float*)d_in[4];  // (2000,)
    const float* idxm   = (const float*)d_in[5];  // (2000,500)
    float* out = (float*)d_out;                   // (730,500,1)

    hbv_scan_kernel<<<125, 256>>>(x, params, wl, Ai, Acb, out);

    dim3 grid((NOUT + BN - 1) / BN, (NSTEP + BM - 1) / BM, SPLITK);
    agg_gemm_kernel<<<grid, 256>>>(idxm, out);
}